// round 7
// baseline (speedup 1.0000x reference)
#include <cuda_runtime.h>
#include <cuda_bf16.h>
#include <cstdint>

// Problem constants (fixed shapes)
#define BB    2
#define NN    20000
#define EE    200000
#define INF   256
#define OUTF  32
#define HEADS 4
#define HDIM  (OUTF * HEADS)   // 128
#define NEG_SLOPE 0.2f

// ---------------- device scratch (no allocations allowed) ----------------
// NOTE: these symbols are ONLY referenced inside device code. Passing them as
// kernel arguments from host code yields the host-side shadow address (silently
// "works" on GB300 via ATS but writes host memory) — the root cause of rounds 1-6.
__device__ float g_xf [(size_t)BB * NN * INF];     // materialized x
__device__ float g_wf [HDIM * INF];                // materialized W
__device__ float g_af [2 * OUTF];                  // materialized a
__device__ float g_h  [(size_t)BB * NN * HDIM];    // h = x@W^T
__device__ float g_sm [(size_t)BB * EE * HEADS];   // per-edge softmax
__device__ float g_aw [(size_t)BB * NN * HEADS];   // aw
__device__ float g_out[(size_t)BB * NN * OUTF];    // output accumulator
__device__ int   g_last[NN];
__device__ int   g_src [EE];
__device__ int   g_dst [EE];
__device__ int   g_bad_int;
__device__ int   g_odd_nonzero;
__device__ int   g_bf16_votes;

// ---------------- kernel 0: init ------------------------------------------
__global__ void init_kernel() {
    int gid = blockIdx.x * blockDim.x + threadIdx.x;
    if (gid < BB * NN * OUTF) g_out[gid] = 0.0f;
    if (gid < NN)             g_last[gid] = -1;
    if (gid == 0) { g_bad_int = 0; g_odd_nonzero = 0; g_bf16_votes = 0; }
}

// ---------------- kernel 1a: probe x dtype (fp32 vs bf16) ------------------
__device__ __forceinline__ bool bf16_plausible(unsigned h) {
    unsigned e = (h >> 7) & 0xFF;
    return (h & 0x7FFF) == 0 || (e >= 100 && e <= 140);
}
__global__ void probe_kernel(const unsigned* __restrict__ w) {
    int i = blockIdx.x * blockDim.x + threadIdx.x;
    if (i >= 4096) return;
    unsigned v = w[i];
    if (bf16_plausible(v & 0xFFFFu) && bf16_plausible(v >> 16))
        atomicAdd(&g_bf16_votes, 1);
}

// ---------------- kernel 1b: materialize float inputs to fp32 --------------
// which: 0 -> g_xf, 1 -> g_wf, 2 -> g_af  (symbol resolved in DEVICE code)
__global__ void fconv_kernel(const void* __restrict__ raw, int which, int n) {
    int i = blockIdx.x * blockDim.x + threadIdx.x;
    if (i >= n) return;
    float* dstp = (which == 0) ? g_xf : (which == 1) ? g_wf : g_af;
    if (g_bf16_votes > 2048) {
        dstp[i] = __bfloat162float(((const __nv_bfloat16*)raw)[i]);
    } else {
        dstp[i] = ((const float*)raw)[i];
    }
}

// ---------------- kernel 2a: 3-way edge dtype detection --------------------
__global__ void detect_kernel(const int* __restrict__ w) {
    int i = blockIdx.x * blockDim.x + threadIdx.x;
    if (i >= 2 * EE) return;
    int v = w[i];
    if (v < 0 || v >= NN)  atomicOr(&g_bad_int, 1);
    if ((i & 1) && v != 0) atomicOr(&g_odd_nonzero, 1);
}

// ---------------- kernel 2b: convert indices to clamped int32 --------------
__global__ void convert_kernel(const void* __restrict__ raw) {
    int e = blockIdx.x * blockDim.x + threadIdx.x;
    if (e >= EE) return;
    int s, d;
    if (g_bad_int) {                 // float32 layout
        const float* p = (const float*)raw;
        s = (int)p[e];  d = (int)p[EE + e];
    } else if (g_odd_nonzero) {      // int32 layout
        const int* p = (const int*)raw;
        s = p[e];       d = p[EE + e];
    } else {                         // int64 layout
        const long long* p = (const long long*)raw;
        s = (int)p[e];  d = (int)p[EE + e];
    }
    g_src[e] = min(max(s, 0), NN - 1);
    g_dst[e] = min(max(d, 0), NN - 1);
}

// ---------------- kernel 3: last edge per src node -------------------------
__global__ void lastedge_kernel() {
    int e = blockIdx.x * blockDim.x + threadIdx.x;
    if (e < EE) atomicMax(&g_last[g_src[e]], e);
}

// ---------------- kernel 4: simple blocked GEMM  H = X @ W^T ---------------
// Writes g_h directly (device-symbol reference, not a parameter).
__global__ __launch_bounds__(256) void gemm_simple() {
    __shared__ float xs[8][INF];
    const int tid = threadIdx.x;
    const int row0 = blockIdx.x * 8;

    for (int i = tid; i < 8 * (INF / 4); i += 256) {
        int r = i >> 6;
        int c = (i & 63) << 2;
        *(float4*)&xs[r][c] = *(const float4*)&g_xf[(size_t)(row0 + r) * INF + c];
    }
    __syncthreads();

    const int col = tid & 127;
    const int rg  = (tid >> 7) * 4;

    float a0 = 0.f, a1 = 0.f, a2 = 0.f, a3 = 0.f;
    for (int k = 0; k < INF; k += 4) {
        float4 w = *(const float4*)&g_wf[(size_t)col * INF + k];
        a0 += xs[rg+0][k]*w.x + xs[rg+0][k+1]*w.y + xs[rg+0][k+2]*w.z + xs[rg+0][k+3]*w.w;
        a1 += xs[rg+1][k]*w.x + xs[rg+1][k+1]*w.y + xs[rg+1][k+2]*w.z + xs[rg+1][k+3]*w.w;
        a2 += xs[rg+2][k]*w.x + xs[rg+2][k+1]*w.y + xs[rg+2][k+2]*w.z + xs[rg+2][k+3]*w.w;
        a3 += xs[rg+3][k]*w.x + xs[rg+3][k+1]*w.y + xs[rg+3][k+2]*w.z + xs[rg+3][k+3]*w.w;
    }
    g_h[(size_t)(row0 + rg + 0) * HDIM + col] = a0;
    g_h[(size_t)(row0 + rg + 1) * HDIM + col] = a1;
    g_h[(size_t)(row0 + rg + 2) * HDIM + col] = a2;
    g_h[(size_t)(row0 + rg + 3) * HDIM + col] = a3;
}

// ---------------- kernel 5: per-edge scores + softmax over batch -----------
__global__ void edgescore_kernel() {
    int gid = blockIdx.x * blockDim.x + threadIdx.x;
    if (gid >= EE * HEADS) return;
    int hh = gid & (HEADS - 1);
    int e  = gid >> 2;
    int s  = g_src[e];
    int d  = g_dst[e];

    float z[BB];
    #pragma unroll
    for (int b = 0; b < BB; b++) {
        const float* hs = g_h + ((size_t)b * NN + s) * HDIM + hh * OUTF;
        const float* hd = g_h + ((size_t)b * NN + d) * HDIM + hh * OUTF;
        float acc = 0.0f;
        #pragma unroll
        for (int f = 0; f < OUTF; f += 4) {
            float4 vs = *(const float4*)(hs + f);
            float4 vd = *(const float4*)(hd + f);
            float4 as = *(const float4*)(g_af + f);
            float4 ad = *(const float4*)(g_af + OUTF + f);
            acc += vs.x*as.x + vs.y*as.y + vs.z*as.z + vs.w*as.w;
            acc += vd.x*ad.x + vd.y*ad.y + vd.z*ad.z + vd.w*ad.w;
        }
        z[b] = acc > 0.0f ? acc : NEG_SLOPE * acc;
    }
    float m  = fmaxf(z[0], z[1]);
    float p0 = __expf(z[0] - m);
    float p1 = __expf(z[1] - m);
    float inv = 1.0f / (p0 + p1);
    g_sm[((size_t)0 * EE + e) * HEADS + hh] = p0 * inv;
    g_sm[((size_t)1 * EE + e) * HEADS + hh] = p1 * inv;
}

// ---------------- kernel 6: aw = sm[:, last_edge] --------------------------
__global__ void aw_kernel() {
    int gid = blockIdx.x * blockDim.x + threadIdx.x;
    if (gid >= NN * HEADS) return;
    int hh = gid & (HEADS - 1);
    int n  = gid >> 2;
    int e  = g_last[n];
    float w0 = 0.0f, w1 = 0.0f;
    if (e >= 0) {
        w0 = g_sm[((size_t)0 * EE + e) * HEADS + hh];
        w1 = g_sm[((size_t)1 * EE + e) * HEADS + hh];
    }
    g_aw[((size_t)0 * NN + n) * HEADS + hh] = w0;
    g_aw[((size_t)1 * NN + n) * HEADS + hh] = w1;
}

// ---------------- kernel 7: aggregation into device scratch ----------------
__global__ __launch_bounds__(256) void agg_kernel() {
    int gid = blockIdx.x * blockDim.x + threadIdx.x;
    if (gid >= EE * BB * (OUTF / 4)) return;
    int f4 = gid & 7;
    int b  = (gid >> 3) & 1;
    int e  = gid >> 4;

    int src = g_src[e];
    int dst = g_dst[e];

    const float* awp = g_aw + ((size_t)b * NN + src) * HEADS;
    float c0 = 0.25f * awp[0];
    float c1 = 0.25f * awp[1];
    float c2 = 0.25f * awp[2];
    float c3 = 0.25f * awp[3];

    const float* hp = g_h + ((size_t)b * NN + dst) * HDIM + f4 * 4;
    float4 h0 = *(const float4*)(hp);
    float4 h1 = *(const float4*)(hp + OUTF);
    float4 h2 = *(const float4*)(hp + 2 * OUTF);
    float4 h3 = *(const float4*)(hp + 3 * OUTF);

    float* op = g_out + ((size_t)b * NN + src) * OUTF + f4 * 4;
    atomicAdd(op + 0, c0 * h0.x + c1 * h1.x + c2 * h2.x + c3 * h3.x);
    atomicAdd(op + 1, c0 * h0.y + c1 * h1.y + c2 * h2.y + c3 * h3.y);
    atomicAdd(op + 2, c0 * h0.z + c1 * h1.z + c2 * h2.z + c3 * h3.z);
    atomicAdd(op + 3, c0 * h0.w + c1 * h1.w + c2 * h2.w + c3 * h3.w);
}

// ---------------- kernel 8: plain-store copy to harness output -------------
__global__ void copyout_kernel(float* __restrict__ out, int out_size) {
    int gid = blockIdx.x * blockDim.x + threadIdx.x;
    int n = BB * NN * OUTF;
    if (gid < n && gid < out_size) out[gid] = g_out[gid];
}

// ---------------- diagnostics (no-ops when healthy) ------------------------
__global__ void check_h_kernel() {
    __shared__ int nz, bad;
    if (threadIdx.x == 0) { nz = 0; bad = 0; }
    __syncthreads();
    for (int i = threadIdx.x; i < 65536; i += blockDim.x) {
        float v = g_h[i];
        if (v != 0.0f)    atomicAdd(&nz, 1);
        if (!isfinite(v)) atomicAdd(&bad, 1);
    }
    __syncthreads();
    if (threadIdx.x == 0 && (nz == 0 || bad > 0)) {
        *(volatile int*)0x8 = 1;   // -> "illegal memory access" = h broken
    }
}
__global__ void check_edges_kernel() {
    __shared__ int cnt;
    if (threadIdx.x == 0) cnt = 0;
    __syncthreads();
    for (int i = threadIdx.x; i < NN; i += blockDim.x)
        if (g_last[i] >= 0) atomicAdd(&cnt, 1);
    __syncthreads();
    if (threadIdx.x == 0 && cnt < 2) {
        for (;;) __nanosleep(1000000);   // -> timeout = edges broken
    }
}

// ---------------- launch ---------------------------------------------------
extern "C" void kernel_launch(void* const* d_in, const int* in_sizes, int n_in,
                              void* d_out, int out_size) {
    // Rank-based binding: largest -> x, 2nd -> edges, 3rd -> W, smallest -> a
    int order[8];
    int m = n_in < 8 ? n_in : 8;
    for (int i = 0; i < m; i++) order[i] = i;
    for (int i = 0; i < m; i++)
        for (int j = i + 1; j < m; j++)
            if (in_sizes[order[j]] > in_sizes[order[i]]) {
                int t = order[i]; order[i] = order[j]; order[j] = t;
            }
    const void* x  = d_in[m > 0 ? order[0] : 0];
    const void* ei = d_in[m > 1 ? order[1] : 1];
    const void* W  = d_in[m > 2 ? order[2] : 2];
    const void* a  = d_in[m > 3 ? order[3] : 3];

    init_kernel<<<(BB * NN * OUTF + 255) / 256, 256>>>();
    probe_kernel<<<16, 256>>>((const unsigned*)x);
    fconv_kernel<<<(BB * NN * INF + 255) / 256, 256>>>(x, 0, BB * NN * INF);
    fconv_kernel<<<(HDIM * INF + 255) / 256, 256>>>(W, 1, HDIM * INF);
    fconv_kernel<<<1, 64>>>(a, 2, 2 * OUTF);
    detect_kernel<<<(2 * EE + 255) / 256, 256>>>((const int*)ei);
    convert_kernel<<<(EE + 255) / 256, 256>>>(ei);
    lastedge_kernel<<<(EE + 255) / 256, 256>>>();
    gemm_simple<<<(BB * NN) / 8, 256>>>();
    edgescore_kernel<<<(EE * HEADS + 255) / 256, 256>>>();
    aw_kernel<<<(NN * HEADS + 255) / 256, 256>>>();
    agg_kernel<<<(EE * BB * (OUTF / 4) + 255) / 256, 256>>>();
    copyout_kernel<<<(BB * NN * OUTF + 255) / 256, 256>>>((float*)d_out, out_size);
    check_h_kernel<<<1, 256>>>();
    check_edges_kernel<<<1, 256>>>();
}

// round 8
// speedup vs baseline: 3.6284x; 3.6284x over previous
#include <cuda_runtime.h>
#include <cuda_bf16.h>
#include <cstdint>

// Problem constants (fixed shapes)
#define BB    2
#define NN    20000
#define EE    200000
#define INF   256
#define OUTF  32
#define HEADS 4
#define HDIM  (OUTF * HEADS)   // 128
#define NEG_SLOPE 0.2f

// ---------------- device scratch ----------------
// CRITICAL: symbols are ONLY referenced inside device code (host-side decay of
// __device__ symbols to shadow addresses was the root cause of rounds 1-6).
__device__ float g_xf [(size_t)BB * NN * INF];     // materialized x
__device__ float g_wf [HDIM * INF];                // materialized W
__device__ float g_af [2 * OUTF];                  // materialized a
__device__ float g_h  [(size_t)BB * NN * HDIM];    // h = x@W^T
__device__ float g_ssrc[(size_t)BB * NN * HEADS];  // per-node src score
__device__ float g_sdst[(size_t)BB * NN * HEADS];  // per-node dst score
__device__ float g_aw [(size_t)BB * NN * HEADS];   // aw * 0.25
__device__ int   g_last[NN];
__device__ int   g_src [EE];
__device__ int   g_dst [EE];
__device__ int   g_bad_int;
__device__ int   g_odd_nonzero;
__device__ int   g_bf16_votes;

// ---------------- kernel 0: init (zero d_out, last=-1, flags) --------------
__global__ void init_kernel(float* __restrict__ out, int out_size) {
    int gid = blockIdx.x * blockDim.x + threadIdx.x;
    if (gid < out_size) out[gid] = 0.0f;
    if (gid < NN)       g_last[gid] = -1;
    if (gid == 0) { g_bad_int = 0; g_odd_nonzero = 0; g_bf16_votes = 0; }
}

// ---------------- kernel 1a: probe x dtype (fp32 vs bf16) ------------------
__device__ __forceinline__ bool bf16_plausible(unsigned h) {
    unsigned e = (h >> 7) & 0xFF;
    return (h & 0x7FFF) == 0 || (e >= 100 && e <= 140);
}
__global__ void probe_kernel(const unsigned* __restrict__ w) {
    int i = blockIdx.x * blockDim.x + threadIdx.x;
    if (i >= 4096) return;
    unsigned v = w[i];
    if (bf16_plausible(v & 0xFFFFu) && bf16_plausible(v >> 16))
        atomicAdd(&g_bf16_votes, 1);
}

// ---------------- kernel 1b: materialize float inputs to fp32 --------------
// which: 0 -> g_xf, 1 -> g_wf, 2 -> g_af  (resolved in DEVICE code)
__global__ void fconv_kernel(const void* __restrict__ raw, int which, int n) {
    int i = blockIdx.x * blockDim.x + threadIdx.x;
    if (i >= n) return;
    float* dstp = (which == 0) ? g_xf : (which == 1) ? g_wf : g_af;
    if (g_bf16_votes > 2048) {
        dstp[i] = __bfloat162float(((const __nv_bfloat16*)raw)[i]);
    } else {
        dstp[i] = ((const float*)raw)[i];
    }
}

// ---------------- kernel 2a: 3-way edge dtype detection --------------------
__global__ void detect_kernel(const int* __restrict__ w) {
    int i = blockIdx.x * blockDim.x + threadIdx.x;
    if (i >= 2 * EE) return;
    int v = w[i];
    if (v < 0 || v >= NN)  atomicOr(&g_bad_int, 1);
    if ((i & 1) && v != 0) atomicOr(&g_odd_nonzero, 1);
}

// ---------------- kernel 2b: convert indices to clamped int32 --------------
__global__ void convert_kernel(const void* __restrict__ raw) {
    int e = blockIdx.x * blockDim.x + threadIdx.x;
    if (e >= EE) return;
    int s, d;
    if (g_bad_int) {                 // float32 layout
        const float* p = (const float*)raw;
        s = (int)p[e];  d = (int)p[EE + e];
    } else if (g_odd_nonzero) {      // int32 layout
        const int* p = (const int*)raw;
        s = p[e];       d = p[EE + e];
    } else {                         // int64 layout
        const long long* p = (const long long*)raw;
        s = (int)p[e];  d = (int)p[EE + e];
    }
    g_src[e] = min(max(s, 0), NN - 1);
    g_dst[e] = min(max(d, 0), NN - 1);
}

// ---------------- kernel 3: last edge per src node -------------------------
__global__ void lastedge_kernel() {
    int e = blockIdx.x * blockDim.x + threadIdx.x;
    if (e < EE) atomicMax(&g_last[g_src[e]], e);
}

// ---------------- kernel 4: tiled fp32 GEMM  g_h = g_xf @ g_wf^T -----------
// BM=64, BN=128 (full width), BK=32, 256 threads, 8x4 register blocking.
#define BM 64
#define BK 32
__global__ __launch_bounds__(256) void gemm_tiled() {
    __shared__ float As[BM][BK];        // 8 KB
    __shared__ float Bs[BK][128 + 4];   // 16.9 KB (row stride 132*4=528, 16B-aligned)

    const int tid = threadIdx.x;
    const int tx  = tid & 31;   // output col group (4 cols)
    const int ty  = tid >> 5;   // output row group (8 rows)
    const int m0  = blockIdx.x * BM;

    float acc[8][4];
    #pragma unroll
    for (int i = 0; i < 8; i++)
        #pragma unroll
        for (int j = 0; j < 4; j++) acc[i][j] = 0.0f;

    for (int k0 = 0; k0 < INF; k0 += BK) {
        {   // A tile: 64x32, float4, coalesced
            int r = tid >> 3;          // 0..31
            int c = (tid & 7) * 4;     // 0..28
            *(float4*)&As[r][c] =
                *(const float4*)&g_xf[(size_t)(m0 + r) * INF + k0 + c];
            *(float4*)&As[r + 32][c] =
                *(const float4*)&g_xf[(size_t)(m0 + r + 32) * INF + k0 + c];
        }
        {   // W tile transposed into Bs[k][n]
            int n = tid >> 3;
            int c = (tid & 7) * 4;
            #pragma unroll
            for (int p = 0; p < 4; p++) {
                float4 w = *(const float4*)&g_wf[(size_t)(n + 32 * p) * INF + k0 + c];
                Bs[c + 0][n + 32 * p] = w.x;
                Bs[c + 1][n + 32 * p] = w.y;
                Bs[c + 2][n + 32 * p] = w.z;
                Bs[c + 3][n + 32 * p] = w.w;
            }
        }
        __syncthreads();

        #pragma unroll
        for (int k = 0; k < BK; k++) {
            float4 bf = *(float4*)&Bs[k][tx * 4];
            float ar[8];
            #pragma unroll
            for (int i = 0; i < 8; i++) ar[i] = As[ty * 8 + i][k];
            #pragma unroll
            for (int i = 0; i < 8; i++) {
                acc[i][0] += ar[i] * bf.x;
                acc[i][1] += ar[i] * bf.y;
                acc[i][2] += ar[i] * bf.z;
                acc[i][3] += ar[i] * bf.w;
            }
        }
        __syncthreads();
    }

    #pragma unroll
    for (int i = 0; i < 8; i++) {
        int m = m0 + ty * 8 + i;
        *(float4*)&g_h[(size_t)m * HDIM + tx * 4] =
            make_float4(acc[i][0], acc[i][1], acc[i][2], acc[i][3]);
    }
}

// ---------------- kernel 5: per-NODE scores (decomposed) -------------------
// score[b,e,h] = ssrc[b,src,h] + sdst[b,dst,h]; compute node dots once.
__global__ void score_kernel() {
    int gid = blockIdx.x * blockDim.x + threadIdx.x;   // (b*NN+n)*HEADS + h
    if (gid >= BB * NN * HEADS) return;
    int hh = gid & (HEADS - 1);
    int bn = gid >> 2;
    const float* hp = g_h + (size_t)bn * HDIM + hh * OUTF;
    float ss = 0.0f, sd = 0.0f;
    #pragma unroll
    for (int f = 0; f < OUTF; f += 4) {
        float4 v  = *(const float4*)(hp + f);
        float4 as = *(const float4*)(g_af + f);
        float4 ad = *(const float4*)(g_af + OUTF + f);
        ss += v.x * as.x + v.y * as.y + v.z * as.z + v.w * as.w;
        sd += v.x * ad.x + v.y * ad.y + v.z * ad.z + v.w * ad.w;
    }
    g_ssrc[gid] = ss;
    g_sdst[gid] = sd;
}

// ---------------- kernel 6: aw from last-edge softmax over batch -----------
__global__ void aw_kernel() {
    int gid = blockIdx.x * blockDim.x + threadIdx.x;   // n*HEADS + h
    if (gid >= NN * HEADS) return;
    int hh = gid & (HEADS - 1);
    int n  = gid >> 2;
    int e  = g_last[n];
    float w0 = 0.0f, w1 = 0.0f;
    if (e >= 0) {
        int d = g_dst[e];
        float z0 = g_ssrc[n * HEADS + hh]        + g_sdst[d * HEADS + hh];
        float z1 = g_ssrc[(NN + n) * HEADS + hh] + g_sdst[(NN + d) * HEADS + hh];
        z0 = z0 > 0.0f ? z0 : NEG_SLOPE * z0;
        z1 = z1 > 0.0f ? z1 : NEG_SLOPE * z1;
        float m  = fmaxf(z0, z1);
        float p0 = __expf(z0 - m);
        float p1 = __expf(z1 - m);
        float inv = 1.0f / (p0 + p1);
        w0 = p0 * inv;
        w1 = p1 * inv;
    }
    g_aw[n * HEADS + hh]        = 0.25f * w0;   // fold head-mean
    g_aw[(NN + n) * HEADS + hh] = 0.25f * w1;
}

// ---------------- kernel 7: aggregation, v4 reductions into d_out ----------
__device__ __forceinline__ void red_add_v4(float* ptr, float4 v) {
    asm volatile("red.global.add.v4.f32 [%0], {%1, %2, %3, %4};"
                 :: "l"(ptr), "f"(v.x), "f"(v.y), "f"(v.z), "f"(v.w)
                 : "memory");
}

__global__ __launch_bounds__(256) void agg_kernel(float* __restrict__ out) {
    int gid = blockIdx.x * blockDim.x + threadIdx.x;
    if (gid >= EE * BB * (OUTF / 4)) return;
    int f4 = gid & 7;          // 0..7
    int b  = (gid >> 3) & 1;
    int e  = gid >> 4;

    int src = g_src[e];
    int dst = g_dst[e];

    float4 c = *(const float4*)(g_aw + ((size_t)b * NN + src) * HEADS);

    const float* hp = g_h + ((size_t)b * NN + dst) * HDIM + f4 * 4;
    float4 h0 = *(const float4*)(hp);
    float4 h1 = *(const float4*)(hp + OUTF);
    float4 h2 = *(const float4*)(hp + 2 * OUTF);
    float4 h3 = *(const float4*)(hp + 3 * OUTF);

    float4 v;
    v.x = c.x * h0.x + c.y * h1.x + c.z * h2.x + c.w * h3.x;
    v.y = c.x * h0.y + c.y * h1.y + c.z * h2.y + c.w * h3.y;
    v.z = c.x * h0.z + c.y * h1.z + c.z * h2.z + c.w * h3.z;
    v.w = c.x * h0.w + c.y * h1.w + c.z * h2.w + c.w * h3.w;

    red_add_v4(out + ((size_t)b * NN + src) * OUTF + f4 * 4, v);
}

// ---------------- launch ---------------------------------------------------
extern "C" void kernel_launch(void* const* d_in, const int* in_sizes, int n_in,
                              void* d_out, int out_size) {
    // Rank-based binding: largest -> x, 2nd -> edges, 3rd -> W, smallest -> a
    int order[8];
    int m = n_in < 8 ? n_in : 8;
    for (int i = 0; i < m; i++) order[i] = i;
    for (int i = 0; i < m; i++)
        for (int j = i + 1; j < m; j++)
            if (in_sizes[order[j]] > in_sizes[order[i]]) {
                int t = order[i]; order[i] = order[j]; order[j] = t;
            }
    const void* x  = d_in[m > 0 ? order[0] : 0];
    const void* ei = d_in[m > 1 ? order[1] : 1];
    const void* W  = d_in[m > 2 ? order[2] : 2];
    const void* a  = d_in[m > 3 ? order[3] : 3];

    float* out = (float*)d_out;

    {
        int n = out_size > NN ? out_size : NN;
        init_kernel<<<(n + 255) / 256, 256>>>(out, out_size);
    }
    probe_kernel<<<16, 256>>>((const unsigned*)x);
    fconv_kernel<<<(BB * NN * INF + 255) / 256, 256>>>(x, 0, BB * NN * INF);
    fconv_kernel<<<(HDIM * INF + 255) / 256, 256>>>(W, 1, HDIM * INF);
    fconv_kernel<<<1, 64>>>(a, 2, 2 * OUTF);
    detect_kernel<<<(2 * EE + 255) / 256, 256>>>((const int*)ei);
    convert_kernel<<<(EE + 255) / 256, 256>>>(ei);
    lastedge_kernel<<<(EE + 255) / 256, 256>>>();
    gemm_tiled<<<(BB * NN) / BM, 256>>>();
    score_kernel<<<(BB * NN * HEADS + 255) / 256, 256>>>();
    aw_kernel<<<(NN * HEADS + 255) / 256, 256>>>();
    agg_kernel<<<(EE * BB * (OUTF / 4) + 255) / 256, 256>>>(out);
}

// round 9
// speedup vs baseline: 4.7533x; 1.3100x over previous
#include <cuda_runtime.h>
#include <cuda_bf16.h>
#include <cstdint>

// Problem constants (fixed shapes)
#define BB    2
#define NN    20000
#define EE    200000
#define INF   256
#define OUTF  32
#define HEADS 4
#define HDIM  (OUTF * HEADS)   // 128
#define NEG_SLOPE 0.2f

// ---------------- device scratch ----------------
// CRITICAL: symbols are ONLY referenced inside device code (host-side decay of
// __device__ symbols is the GB300 ATS silent-corruption trap from rounds 1-6).
__device__ float g_wf [HDIM * INF];                // materialized W
__device__ float g_af [2 * OUTF];                  // materialized a
__device__ float g_h  [(size_t)BB * NN * HDIM];    // h = x@W^T
__device__ float g_ssrc[(size_t)BB * NN * HEADS];  // per-node src score
__device__ float g_sdst[(size_t)BB * NN * HEADS];  // per-node dst score
__device__ float g_aw [(size_t)BB * NN * HEADS];   // aw * 0.25
__device__ int   g_last[NN];
__device__ int   g_src [EE];
__device__ int   g_dst [EE];
__device__ int   g_bad_int;
__device__ int   g_odd_nonzero;
__device__ int   g_bf16_votes;

// ---------------- kernel 0: init (zero d_out, last=-1, flags) --------------
__global__ void init_kernel(float* __restrict__ out, int out_size) {
    int gid = blockIdx.x * blockDim.x + threadIdx.x;
    if (gid < out_size) out[gid] = 0.0f;
    if (gid < NN)       g_last[gid] = -1;
    if (gid == 0) { g_bad_int = 0; g_odd_nonzero = 0; g_bf16_votes = 0; }
}

// ---------------- kernel 1a: probe x dtype (fp32 vs bf16) ------------------
__device__ __forceinline__ bool bf16_plausible(unsigned h) {
    unsigned e = (h >> 7) & 0xFF;
    return (h & 0x7FFF) == 0 || (e >= 100 && e <= 140);
}
__global__ void probe_kernel(const unsigned* __restrict__ w) {
    int i = blockIdx.x * blockDim.x + threadIdx.x;
    if (i >= 4096) return;
    unsigned v = w[i];
    if (bf16_plausible(v & 0xFFFFu) && bf16_plausible(v >> 16))
        atomicAdd(&g_bf16_votes, 1);
}

// ---------------- kernel 1b: materialize W / a to fp32 ---------------------
// which: 1 -> g_wf, 2 -> g_af  (resolved in DEVICE code)
__global__ void fconv_kernel(const void* __restrict__ raw, int which, int n) {
    int i = blockIdx.x * blockDim.x + threadIdx.x;
    if (i >= n) return;
    float* dstp = (which == 1) ? g_wf : g_af;
    if (g_bf16_votes > 2048) {
        dstp[i] = __bfloat162float(((const __nv_bfloat16*)raw)[i]);
    } else {
        dstp[i] = ((const float*)raw)[i];
    }
}

// ---------------- kernel 2a: 3-way edge dtype detection --------------------
__global__ void detect_kernel(const int* __restrict__ w) {
    int i = blockIdx.x * blockDim.x + threadIdx.x;
    if (i >= 2 * EE) return;
    int v = w[i];
    if (v < 0 || v >= NN)  atomicOr(&g_bad_int, 1);
    if ((i & 1) && v != 0) atomicOr(&g_odd_nonzero, 1);
}

// ---------------- kernel 3: tiled fp32 GEMM  g_h = x @ g_wf^T --------------
// Reads raw x with device-side dtype branch (no materialization round-trip).
// BM=64, BN=128 (full width), BK=32, 256 threads, 8x4 register blocking.
#define BM 64
#define BK 32
__global__ __launch_bounds__(256) void gemm_tiled(const void* __restrict__ xraw) {
    __shared__ float As[BM][BK];        // 8 KB
    __shared__ float Bs[BK][128 + 4];   // 16.9 KB

    const int tid = threadIdx.x;
    const int tx  = tid & 31;   // output col group (4 cols)
    const int ty  = tid >> 5;   // output row group (8 rows)
    const int m0  = blockIdx.x * BM;
    const bool is_bf16 = (g_bf16_votes > 2048);

    float acc[8][4];
    #pragma unroll
    for (int i = 0; i < 8; i++)
        #pragma unroll
        for (int j = 0; j < 4; j++) acc[i][j] = 0.0f;

    for (int k0 = 0; k0 < INF; k0 += BK) {
        {   // A tile: 64x32, coalesced; dtype branch on raw x
            int r = tid >> 3;          // 0..31
            int c = (tid & 7) * 4;     // 0..28
            if (!is_bf16) {
                const float* X = (const float*)xraw;
                *(float4*)&As[r][c] =
                    *(const float4*)&X[(size_t)(m0 + r) * INF + k0 + c];
                *(float4*)&As[r + 32][c] =
                    *(const float4*)&X[(size_t)(m0 + r + 32) * INF + k0 + c];
            } else {
                const __nv_bfloat16* X = (const __nv_bfloat16*)xraw;
                #pragma unroll
                for (int rr = 0; rr < 2; rr++) {
                    const __nv_bfloat16* p =
                        X + (size_t)(m0 + r + rr * 32) * INF + k0 + c;
                    float2 lo = __bfloat1622float2(*(const __nv_bfloat162*)(p));
                    float2 hi = __bfloat1622float2(*(const __nv_bfloat162*)(p + 2));
                    *(float4*)&As[r + rr * 32][c] =
                        make_float4(lo.x, lo.y, hi.x, hi.y);
                }
            }
        }
        {   // W tile transposed into Bs[k][n]
            int n = tid >> 3;
            int c = (tid & 7) * 4;
            #pragma unroll
            for (int p = 0; p < 4; p++) {
                float4 w = *(const float4*)&g_wf[(size_t)(n + 32 * p) * INF + k0 + c];
                Bs[c + 0][n + 32 * p] = w.x;
                Bs[c + 1][n + 32 * p] = w.y;
                Bs[c + 2][n + 32 * p] = w.z;
                Bs[c + 3][n + 32 * p] = w.w;
            }
        }
        __syncthreads();

        #pragma unroll
        for (int k = 0; k < BK; k++) {
            float4 bf = *(float4*)&Bs[k][tx * 4];
            float ar[8];
            #pragma unroll
            for (int i = 0; i < 8; i++) ar[i] = As[ty * 8 + i][k];
            #pragma unroll
            for (int i = 0; i < 8; i++) {
                acc[i][0] += ar[i] * bf.x;
                acc[i][1] += ar[i] * bf.y;
                acc[i][2] += ar[i] * bf.z;
                acc[i][3] += ar[i] * bf.w;
            }
        }
        __syncthreads();
    }

    #pragma unroll
    for (int i = 0; i < 8; i++) {
        int m = m0 + ty * 8 + i;
        *(float4*)&g_h[(size_t)m * HDIM + tx * 4] =
            make_float4(acc[i][0], acc[i][1], acc[i][2], acc[i][3]);
    }
}

// ---------------- kernel 4: convert indices to clamped int32 ---------------
__global__ void convert_kernel(const void* __restrict__ raw) {
    int e = blockIdx.x * blockDim.x + threadIdx.x;
    if (e >= EE) return;
    int s, d;
    if (g_bad_int) {                 // float32 layout
        const float* p = (const float*)raw;
        s = (int)p[e];  d = (int)p[EE + e];
    } else if (g_odd_nonzero) {      // int32 layout
        const int* p = (const int*)raw;
        s = p[e];       d = p[EE + e];
    } else {                         // int64 layout
        const long long* p = (const long long*)raw;
        s = (int)p[e];  d = (int)p[EE + e];
    }
    g_src[e] = min(max(s, 0), NN - 1);
    g_dst[e] = min(max(d, 0), NN - 1);
}

// ---------------- kernel 5: last edge per src node -------------------------
__global__ void lastedge_kernel() {
    int e = blockIdx.x * blockDim.x + threadIdx.x;
    if (e < EE) atomicMax(&g_last[g_src[e]], e);
}

// ---------------- kernel 6: per-NODE scores (decomposed) -------------------
__global__ void score_kernel() {
    int gid = blockIdx.x * blockDim.x + threadIdx.x;   // (b*NN+n)*HEADS + h
    if (gid >= BB * NN * HEADS) return;
    int hh = gid & (HEADS - 1);
    int bn = gid >> 2;
    const float* hp = g_h + (size_t)bn * HDIM + hh * OUTF;
    float ss = 0.0f, sd = 0.0f;
    #pragma unroll
    for (int f = 0; f < OUTF; f += 4) {
        float4 v  = *(const float4*)(hp + f);
        float4 as = *(const float4*)(g_af + f);
        float4 ad = *(const float4*)(g_af + OUTF + f);
        ss += v.x * as.x + v.y * as.y + v.z * as.z + v.w * as.w;
        sd += v.x * ad.x + v.y * ad.y + v.z * ad.z + v.w * ad.w;
    }
    g_ssrc[gid] = ss;
    g_sdst[gid] = sd;
}

// ---------------- kernel 7: aw from last-edge softmax over batch -----------
__global__ void aw_kernel() {
    int gid = blockIdx.x * blockDim.x + threadIdx.x;   // n*HEADS + h
    if (gid >= NN * HEADS) return;
    int hh = gid & (HEADS - 1);
    int n  = gid >> 2;
    int e  = g_last[n];
    float w0 = 0.0f, w1 = 0.0f;
    if (e >= 0) {
        int d = g_dst[e];
        float z0 = g_ssrc[n * HEADS + hh]        + g_sdst[d * HEADS + hh];
        float z1 = g_ssrc[(NN + n) * HEADS + hh] + g_sdst[(NN + d) * HEADS + hh];
        z0 = z0 > 0.0f ? z0 : NEG_SLOPE * z0;
        z1 = z1 > 0.0f ? z1 : NEG_SLOPE * z1;
        float m  = fmaxf(z0, z1);
        float p0 = __expf(z0 - m);
        float p1 = __expf(z1 - m);
        float inv = 1.0f / (p0 + p1);
        w0 = p0 * inv;
        w1 = p1 * inv;
    }
    g_aw[n * HEADS + hh]        = 0.25f * w0;   // fold head-mean
    g_aw[(NN + n) * HEADS + hh] = 0.25f * w1;
}

// ---------------- kernel 8: aggregation, v4 reductions into d_out ----------
__device__ __forceinline__ void red_add_v4(float* ptr, float4 v) {
    asm volatile("red.global.add.v4.f32 [%0], {%1, %2, %3, %4};"
                 :: "l"(ptr), "f"(v.x), "f"(v.y), "f"(v.z), "f"(v.w)
                 : "memory");
}

__global__ __launch_bounds__(256) void agg_kernel(float* __restrict__ out) {
    int gid = blockIdx.x * blockDim.x + threadIdx.x;
    if (gid >= EE * BB * (OUTF / 4)) return;
    int f4 = gid & 7;          // 0..7
    int b  = (gid >> 3) & 1;
    int e  = gid >> 4;

    int src = g_src[e];
    int dst = g_dst[e];

    float4 c = *(const float4*)(g_aw + ((size_t)b * NN + src) * HEADS);

    const float* hp = g_h + ((size_t)b * NN + dst) * HDIM + f4 * 4;
    float4 h0 = __ldg((const float4*)(hp));
    float4 h1 = __ldg((const float4*)(hp + OUTF));
    float4 h2 = __ldg((const float4*)(hp + 2 * OUTF));
    float4 h3 = __ldg((const float4*)(hp + 3 * OUTF));

    float4 v;
    v.x = c.x * h0.x + c.y * h1.x + c.z * h2.x + c.w * h3.x;
    v.y = c.x * h0.y + c.y * h1.y + c.z * h2.y + c.w * h3.y;
    v.z = c.x * h0.z + c.y * h1.z + c.z * h2.z + c.w * h3.z;
    v.w = c.x * h0.w + c.y * h1.w + c.z * h2.w + c.w * h3.w;

    red_add_v4(out + ((size_t)b * NN + src) * OUTF + f4 * 4, v);
}

// ---------------- launch ---------------------------------------------------
extern "C" void kernel_launch(void* const* d_in, const int* in_sizes, int n_in,
                              void* d_out, int out_size) {
    // Rank-based binding: largest -> x, 2nd -> edges, 3rd -> W, smallest -> a
    int order[8];
    int m = n_in < 8 ? n_in : 8;
    for (int i = 0; i < m; i++) order[i] = i;
    for (int i = 0; i < m; i++)
        for (int j = i + 1; j < m; j++)
            if (in_sizes[order[j]] > in_sizes[order[i]]) {
                int t = order[i]; order[i] = order[j]; order[j] = t;
            }
    const void* x  = d_in[m > 0 ? order[0] : 0];
    const void* ei = d_in[m > 1 ? order[1] : 1];
    const void* W  = d_in[m > 2 ? order[2] : 2];
    const void* a  = d_in[m > 3 ? order[3] : 3];

    float* out = (float*)d_out;

    // Launch order puts gemm_tiled at position 6 so ncu (-s 5 -c 1) captures it.
    {
        int n = out_size > NN ? out_size : NN;
        init_kernel<<<(n + 255) / 256, 256>>>(out, out_size);            // 1
    }
    probe_kernel<<<16, 256>>>((const unsigned*)x);                        // 2
    fconv_kernel<<<(HDIM * INF + 255) / 256, 256>>>(W, 1, HDIM * INF);    // 3
    fconv_kernel<<<1, 64>>>(a, 2, 2 * OUTF);                              // 4
    detect_kernel<<<(2 * EE + 255) / 256, 256>>>((const int*)ei);         // 5
    gemm_tiled<<<(BB * NN) / BM, 256>>>(x);                               // 6 <- profiled
    convert_kernel<<<(EE + 255) / 256, 256>>>(ei);                        // 7
    lastedge_kernel<<<(EE + 255) / 256, 256>>>();                         // 8
    score_kernel<<<(BB * NN * HEADS + 255) / 256, 256>>>();               // 9
    aw_kernel<<<(NN * HEADS + 255) / 256, 256>>>();                       // 10
    agg_kernel<<<(EE * BB * (OUTF / 4) + 255) / 256, 256>>>(out);         // 11
}

// round 10
// speedup vs baseline: 7.1923x; 1.5131x over previous
#include <cuda_runtime.h>
#include <cuda_bf16.h>
#include <cstdint>

// Problem constants (fixed shapes)
#define BB    2
#define NN    20000
#define EE    200000
#define INF   256
#define OUTF  32
#define HEADS 4
#define HDIM  (OUTF * HEADS)   // 128
#define NEG_SLOPE 0.2f

// ---------------- device scratch ----------------
// CRITICAL: symbols are ONLY referenced inside device code (host-side decay of
// __device__ symbols is the GB300 ATS silent-corruption trap from rounds 1-6).
__device__ float g_wf [HDIM * INF];                // W, pre-rounded to tf32 bits
__device__ float g_af [2 * OUTF];                  // a (fp32)
__device__ float g_h  [(size_t)BB * NN * HDIM];    // h = x@W^T
__device__ float g_ssrc[(size_t)BB * NN * HEADS];  // per-node src score
__device__ float g_sdst[(size_t)BB * NN * HEADS];  // per-node dst score
__device__ float g_aw [(size_t)BB * NN * HEADS];   // aw * 0.25
__device__ int   g_last[NN];
__device__ int   g_src [EE];
__device__ int   g_dst [EE];
__device__ int   g_bad_int;
__device__ int   g_odd_nonzero;
__device__ int   g_bf16_votes;

__device__ __forceinline__ uint32_t f2tf32(float f) {
    uint32_t r;
    asm("cvt.rna.tf32.f32 %0, %1;" : "=r"(r) : "f"(f));
    return r;
}

// ---------------- kernel 0: init (zero d_out, last=-1, flags) --------------
__global__ void init_kernel(float* __restrict__ out, int out_size) {
    int gid = blockIdx.x * blockDim.x + threadIdx.x;
    if (gid < out_size) out[gid] = 0.0f;
    if (gid < NN)       g_last[gid] = -1;
    if (gid == 0) { g_bad_int = 0; g_odd_nonzero = 0; g_bf16_votes = 0; }
}

// ---------------- kernel 1a: probe x dtype (fp32 vs bf16) ------------------
__device__ __forceinline__ bool bf16_plausible(unsigned h) {
    unsigned e = (h >> 7) & 0xFF;
    return (h & 0x7FFF) == 0 || (e >= 100 && e <= 140);
}
__global__ void probe_kernel(const unsigned* __restrict__ w) {
    int i = blockIdx.x * blockDim.x + threadIdx.x;
    if (i >= 4096) return;
    unsigned v = w[i];
    if (bf16_plausible(v & 0xFFFFu) && bf16_plausible(v >> 16))
        atomicAdd(&g_bf16_votes, 1);
}

// ---------------- kernel 1b: materialize W (as tf32 bits) / a (fp32) -------
// which: 1 -> g_wf (tf32-rounded), 2 -> g_af (fp32). Resolved in DEVICE code.
__global__ void fconv_kernel(const void* __restrict__ raw, int which, int n) {
    int i = blockIdx.x * blockDim.x + threadIdx.x;
    if (i >= n) return;
    float v;
    if (g_bf16_votes > 2048) v = __bfloat162float(((const __nv_bfloat16*)raw)[i]);
    else                     v = ((const float*)raw)[i];
    if (which == 1) {
        uint32_t t = f2tf32(v);
        g_wf[i] = __uint_as_float(t);
    } else {
        g_af[i] = v;
    }
}

// ---------------- kernel 2: 3-way edge dtype detection ---------------------
__global__ void detect_kernel(const int* __restrict__ w) {
    int i = blockIdx.x * blockDim.x + threadIdx.x;
    if (i >= 2 * EE) return;
    int v = w[i];
    if (v < 0 || v >= NN)  atomicOr(&g_bad_int, 1);
    if ((i & 1) && v != 0) atomicOr(&g_odd_nonzero, 1);
}

// ---------------- kernel 3: tf32 tensor-core GEMM  g_h = x @ W^T -----------
// BM=64, BN=128, BK=32. 256 threads = 8 warps; warp w: M quad (w&3)*16,
// N half (w>>2)*64 (8 n-tiles of 8). mma.m16n8k8.tf32, fp32 accumulate.
// Smem row stride 36: fragment LDS bank = (4g+t) mod 32, conflict-free.
#define BM 64
#define BK 32
#define SSTRIDE 36
__global__ __launch_bounds__(256) void gemm_tf32(const void* __restrict__ xraw) {
    __shared__ uint32_t As[BM * SSTRIDE];        // 9.2 KB
    __shared__ uint32_t Bs[HDIM * SSTRIDE];      // 18.4 KB

    const int tid  = threadIdx.x;
    const int lane = tid & 31;
    const int g    = lane >> 2;        // 0..7
    const int t    = lane & 3;         // 0..3
    const int mw   = (tid >> 5) & 3;   // M quadrant
    const int nh   = tid >> 7;         // N half
    const int m0   = blockIdx.x * BM;
    const bool is_bf16 = (g_bf16_votes > 2048);

    float acc[8][4];
    #pragma unroll
    for (int i = 0; i < 8; i++)
        #pragma unroll
        for (int j = 0; j < 4; j++) acc[i][j] = 0.0f;

    for (int k0 = 0; k0 < INF; k0 += BK) {
        {   // A tile: 64 rows x 32 k, convert to tf32, store via uint4
            int r = tid >> 3;          // 0..31
            int c = (tid & 7) * 4;     // 0..28
            #pragma unroll
            for (int rr = 0; rr < 2; rr++) {
                int row = r + rr * 32;
                float4 f;
                if (!is_bf16) {
                    f = *(const float4*)((const float*)xraw +
                        (size_t)(m0 + row) * INF + k0 + c);
                } else {
                    const __nv_bfloat16* p = (const __nv_bfloat16*)xraw +
                        (size_t)(m0 + row) * INF + k0 + c;
                    float2 lo = __bfloat1622float2(*(const __nv_bfloat162*)(p));
                    float2 hi = __bfloat1622float2(*(const __nv_bfloat162*)(p + 2));
                    f = make_float4(lo.x, lo.y, hi.x, hi.y);
                }
                uint4 u = make_uint4(f2tf32(f.x), f2tf32(f.y),
                                     f2tf32(f.z), f2tf32(f.w));
                *(uint4*)&As[row * SSTRIDE + c] = u;   // 16B-aligned (144*r+4c)
            }
        }
        {   // B tile: 128 n-rows x 32 k from g_wf (already tf32 bits), copy
            #pragma unroll
            for (int p = 0; p < 4; p++) {
                int idx = tid + p * 256;
                int n = idx >> 3;            // 0..127
                int c = (idx & 7) * 4;       // 0..28
                uint4 u = *(const uint4*)((const uint32_t*)g_wf +
                                          (size_t)n * INF + k0 + c);
                *(uint4*)&Bs[n * SSTRIDE + c] = u;
            }
        }
        __syncthreads();

        #pragma unroll
        for (int kk = 0; kk < BK; kk += 8) {
            const uint32_t* ap = &As[(mw * 16 + g) * SSTRIDE + kk + t];
            uint32_t a0 = ap[0];
            uint32_t a1 = ap[8 * SSTRIDE];
            uint32_t a2 = ap[4];
            uint32_t a3 = ap[8 * SSTRIDE + 4];
            #pragma unroll
            for (int nt = 0; nt < 8; nt++) {
                const uint32_t* bp = &Bs[(nh * 64 + nt * 8 + g) * SSTRIDE + kk + t];
                uint32_t b0 = bp[0];
                uint32_t b1 = bp[4];
                asm volatile(
                    "mma.sync.aligned.m16n8k8.row.col.f32.tf32.tf32.f32 "
                    "{%0,%1,%2,%3}, {%4,%5,%6,%7}, {%8,%9}, {%0,%1,%2,%3};"
                    : "+f"(acc[nt][0]), "+f"(acc[nt][1]),
                      "+f"(acc[nt][2]), "+f"(acc[nt][3])
                    : "r"(a0), "r"(a1), "r"(a2), "r"(a3), "r"(b0), "r"(b1));
            }
        }
        __syncthreads();
    }

    // Epilogue: D frag c0=(g,2t) c1=(g,2t+1) c2=(g+8,2t) c3=(g+8,2t+1)
    int mrow = m0 + mw * 16 + g;
    #pragma unroll
    for (int nt = 0; nt < 8; nt++) {
        int ncol = nh * 64 + nt * 8 + 2 * t;
        *(float2*)&g_h[(size_t)mrow * HDIM + ncol] =
            make_float2(acc[nt][0], acc[nt][1]);
        *(float2*)&g_h[(size_t)(mrow + 8) * HDIM + ncol] =
            make_float2(acc[nt][2], acc[nt][3]);
    }
}

// ---------------- kernel 4: convert indices + last-edge (fused) ------------
__global__ void convert_lastedge_kernel(const void* __restrict__ raw) {
    int e = blockIdx.x * blockDim.x + threadIdx.x;
    if (e >= EE) return;
    int s, d;
    if (g_bad_int) {                 // float32 layout
        const float* p = (const float*)raw;
        s = (int)p[e];  d = (int)p[EE + e];
    } else if (g_odd_nonzero) {      // int32 layout
        const int* p = (const int*)raw;
        s = p[e];       d = p[EE + e];
    } else {                         // int64 layout
        const long long* p = (const long long*)raw;
        s = (int)p[e];  d = (int)p[EE + e];
    }
    s = min(max(s, 0), NN - 1);
    d = min(max(d, 0), NN - 1);
    g_src[e] = s;
    g_dst[e] = d;
    atomicMax(&g_last[s], e);
}

// ---------------- kernel 5: per-NODE scores (decomposed) -------------------
__global__ void score_kernel() {
    int gid = blockIdx.x * blockDim.x + threadIdx.x;   // (b*NN+n)*HEADS + h
    if (gid >= BB * NN * HEADS) return;
    int hh = gid & (HEADS - 1);
    int bn = gid >> 2;
    const float* hp = g_h + (size_t)bn * HDIM + hh * OUTF;
    float ss = 0.0f, sd = 0.0f;
    #pragma unroll
    for (int f = 0; f < OUTF; f += 4) {
        float4 v  = *(const float4*)(hp + f);
        float4 as = *(const float4*)(g_af + f);
        float4 ad = *(const float4*)(g_af + OUTF + f);
        ss += v.x * as.x + v.y * as.y + v.z * as.z + v.w * as.w;
        sd += v.x * ad.x + v.y * ad.y + v.z * ad.z + v.w * ad.w;
    }
    g_ssrc[gid] = ss;
    g_sdst[gid] = sd;
}

// ---------------- kernel 6: aw from last-edge softmax over batch -----------
__global__ void aw_kernel() {
    int gid = blockIdx.x * blockDim.x + threadIdx.x;   // n*HEADS + h
    if (gid >= NN * HEADS) return;
    int hh = gid & (HEADS - 1);
    int n  = gid >> 2;
    int e  = g_last[n];
    float w0 = 0.0f, w1 = 0.0f;
    if (e >= 0) {
        int d = g_dst[e];
        float z0 = g_ssrc[n * HEADS + hh]        + g_sdst[d * HEADS + hh];
        float z1 = g_ssrc[(NN + n) * HEADS + hh] + g_sdst[(NN + d) * HEADS + hh];
        z0 = z0 > 0.0f ? z0 : NEG_SLOPE * z0;
        z1 = z1 > 0.0f ? z1 : NEG_SLOPE * z1;
        float m  = fmaxf(z0, z1);
        float p0 = __expf(z0 - m);
        float p1 = __expf(z1 - m);
        float inv = 1.0f / (p0 + p1);
        w0 = p0 * inv;
        w1 = p1 * inv;
    }
    g_aw[n * HEADS + hh]        = 0.25f * w0;   // fold head-mean
    g_aw[(NN + n) * HEADS + hh] = 0.25f * w1;
}

// ---------------- kernel 7: aggregation, v4 reductions into d_out ----------
__device__ __forceinline__ void red_add_v4(float* ptr, float4 v) {
    asm volatile("red.global.add.v4.f32 [%0], {%1, %2, %3, %4};"
                 :: "l"(ptr), "f"(v.x), "f"(v.y), "f"(v.z), "f"(v.w)
                 : "memory");
}

__global__ __launch_bounds__(256) void agg_kernel(float* __restrict__ out) {
    int gid = blockIdx.x * blockDim.x + threadIdx.x;
    if (gid >= EE * BB * (OUTF / 4)) return;
    int f4 = gid & 7;          // 0..7
    int b  = (gid >> 3) & 1;
    int e  = gid >> 4;

    int src = g_src[e];
    int dst = g_dst[e];

    float4 c = *(const float4*)(g_aw + ((size_t)b * NN + src) * HEADS);

    const float* hp = g_h + ((size_t)b * NN + dst) * HDIM + f4 * 4;
    float4 h0 = __ldg((const float4*)(hp));
    float4 h1 = __ldg((const float4*)(hp + OUTF));
    float4 h2 = __ldg((const float4*)(hp + 2 * OUTF));
    float4 h3 = __ldg((const float4*)(hp + 3 * OUTF));

    float4 v;
    v.x = c.x * h0.x + c.y * h1.x + c.z * h2.x + c.w * h3.x;
    v.y = c.x * h0.y + c.y * h1.y + c.z * h2.y + c.w * h3.y;
    v.z = c.x * h0.z + c.y * h1.z + c.z * h2.z + c.w * h3.z;
    v.w = c.x * h0.w + c.y * h1.w + c.z * h2.w + c.w * h3.w;

    red_add_v4(out + ((size_t)b * NN + src) * OUTF + f4 * 4, v);
}

// ---------------- launch ---------------------------------------------------
extern "C" void kernel_launch(void* const* d_in, const int* in_sizes, int n_in,
                              void* d_out, int out_size) {
    // Rank-based binding: largest -> x, 2nd -> edges, 3rd -> W, smallest -> a
    int order[8];
    int m = n_in < 8 ? n_in : 8;
    for (int i = 0; i < m; i++) order[i] = i;
    for (int i = 0; i < m; i++)
        for (int j = i + 1; j < m; j++)
            if (in_sizes[order[j]] > in_sizes[order[i]]) {
                int t = order[i]; order[i] = order[j]; order[j] = t;
            }
    const void* x  = d_in[m > 0 ? order[0] : 0];
    const void* ei = d_in[m > 1 ? order[1] : 1];
    const void* W  = d_in[m > 2 ? order[2] : 2];
    const void* a  = d_in[m > 3 ? order[3] : 3];

    float* out = (float*)d_out;

    // gemm at launch position 4 — the slot ncu has been capturing.
    {
        int n = out_size > NN ? out_size : NN;
        init_kernel<<<(n + 255) / 256, 256>>>(out, out_size);            // 1
    }
    probe_kernel<<<16, 256>>>((const unsigned*)x);                        // 2
    fconv_kernel<<<(HDIM * INF + 255) / 256, 256>>>(W, 1, HDIM * INF);    // 3
    gemm_tf32<<<(BB * NN) / BM, 256>>>(x);                                // 4 <- profiled
    fconv_kernel<<<1, 64>>>(a, 2, 2 * OUTF);                              // 5
    detect_kernel<<<(2 * EE + 255) / 256, 256>>>((const int*)ei);         // 6
    convert_lastedge_kernel<<<(EE + 255) / 256, 256>>>(ei);               // 7
    score_kernel<<<(BB * NN * HEADS + 255) / 256, 256>>>();               // 8
    aw_kernel<<<(NN * HEADS + 255) / 256, 256>>>();                       // 9
    agg_kernel<<<(EE * BB * (OUTF / 4) + 255) / 256, 256>>>(out);         // 10
}

// round 11
// speedup vs baseline: 8.2608x; 1.1486x over previous
#include <cuda_runtime.h>
#include <cuda_bf16.h>
#include <cstdint>

// Problem constants (fixed shapes)
#define BB    2
#define NN    20000
#define EE    200000
#define INF   256
#define OUTF  32
#define HEADS 4
#define HDIM  (OUTF * HEADS)   // 128
#define NEG_SLOPE 0.2f

// ---------------- device scratch ----------------
// CRITICAL: symbols are ONLY referenced inside device code (host-side decay of
// __device__ symbols is the GB300 ATS silent-corruption trap from rounds 1-6).
__device__ float g_wf [HDIM * INF];                // W, pre-rounded to tf32 bits
__device__ float g_af [2 * OUTF];                  // a (fp32)
__device__ float g_h  [(size_t)BB * NN * HDIM];    // h = x@W^T
__device__ float g_ssrc[(size_t)BB * NN * HEADS];  // per-node src score
__device__ float g_sdst[(size_t)BB * NN * HEADS];  // per-node dst score
__device__ float g_aw [(size_t)BB * NN * HEADS];   // aw * 0.25
__device__ int   g_last[NN];
__device__ int   g_src [EE];
__device__ int   g_dst [EE];
__device__ int   g_bad_int;
__device__ int   g_odd_nonzero;
__device__ int   g_is_bf16;

__device__ __forceinline__ uint32_t f2tf32(float f) {
    uint32_t r;
    asm("cvt.rna.tf32.f32 %0, %1;" : "=r"(r) : "f"(f));
    return r;
}

#define CP_ASYNC16(smem_u32, gptr) \
    asm volatile("cp.async.cg.shared.global [%0], [%1], 16;" \
                 :: "r"(smem_u32), "l"(gptr))
#define CP_COMMIT() asm volatile("cp.async.commit_group;" ::: "memory")
#define CP_WAIT0()  asm volatile("cp.async.wait_group 0;" ::: "memory")

// ---------------- kernel 1: init + dtype probe (fused) ---------------------
// Block 0 performs the fp32-vs-bf16 probe via __syncthreads_count ballot —
// overwrite semantics, safe under graph replay (no accumulating counter).
__global__ void init_probe_kernel(float* __restrict__ out, int out_size,
                                  const unsigned* __restrict__ xw) {
    int gid = blockIdx.x * blockDim.x + threadIdx.x;
    if (gid < out_size) out[gid] = 0.0f;
    if (gid < NN)       g_last[gid] = -1;
    if (gid == 0) { g_bad_int = 0; g_odd_nonzero = 0; }

    if (blockIdx.x == 0) {
        // each thread checks 16 words of x; bf16-packed => both halves plausible
        bool all_ok = true;
        for (int j = 0; j < 16; j++) {
            unsigned v = xw[threadIdx.x * 16 + j];
            unsigned lo = v & 0xFFFFu, hi = v >> 16;
            unsigned el = (lo >> 7) & 0xFF, eh = (hi >> 7) & 0xFF;
            bool okl = (lo & 0x7FFF) == 0 || (el >= 100 && el <= 140);
            bool okh = (hi & 0x7FFF) == 0 || (eh >= 100 && eh <= 140);
            all_ok &= (okl && okh);
        }
        int cnt = __syncthreads_count(all_ok);
        if (threadIdx.x == 0) g_is_bf16 = (cnt > 128) ? 1 : 0;
    }
}

// ---------------- kernel 2: materialize W (tf32 bits) + a (fp32) -----------
__global__ void fconv_all_kernel(const void* __restrict__ Wraw,
                                 const void* __restrict__ araw) {
    int i = blockIdx.x * blockDim.x + threadIdx.x;
    bool bf = (g_is_bf16 != 0);
    if (i < HDIM * INF) {
        float v = bf ? __bfloat162float(((const __nv_bfloat16*)Wraw)[i])
                     : ((const float*)Wraw)[i];
        g_wf[i] = __uint_as_float(f2tf32(v));
    } else if (i < HDIM * INF + 2 * OUTF) {
        int j = i - HDIM * INF;
        float v = bf ? __bfloat162float(((const __nv_bfloat16*)araw)[j])
                     : ((const float*)araw)[j];
        g_af[j] = v;
    }
}

// ---------------- kernel 3: 3-way edge dtype detection ---------------------
__global__ void detect_kernel(const int* __restrict__ w) {
    int i = blockIdx.x * blockDim.x + threadIdx.x;
    if (i >= 2 * EE) return;
    int v = w[i];
    if (v < 0 || v >= NN)  atomicOr(&g_bad_int, 1);
    if ((i & 1) && v != 0) atomicOr(&g_odd_nonzero, 1);
}

// ---------------- kernel 4: pipelined tf32 GEMM + fused scores -------------
// BM=64 rows x BN=64 cols per block, grid (625, 2). BK=32, 2-stage cp.async.
// 8 warps: mw = warp&3 (16-row quad), nh2 = warp>>2 (32-col half = ONE head).
// Epilogue computes ssrc/sdst per (row, head) via 2 shfl reductions.
#define BM 64
#define BK 32
#define SSTRIDE 36
__global__ __launch_bounds__(256) void gemm_tf32(const void* __restrict__ xraw) {
    __shared__ float As[2][BM * SSTRIDE];   // 2 x 9.2 KB
    __shared__ float Bs[2][64 * SSTRIDE];   // 2 x 9.2 KB   (36.9 KB total)

    const int tid  = threadIdx.x;
    const int lane = tid & 31;
    const int g    = lane >> 2;        // 0..7
    const int t    = lane & 3;         // 0..3
    const int warp = tid >> 5;
    const int mw   = warp & 3;
    const int nh2  = warp >> 2;        // 0 or 1
    const int m0   = blockIdx.x * BM;
    const int n0   = blockIdx.y * 64;
    const bool is_bf16 = (g_is_bf16 != 0);

    const int pr = tid >> 3;           // 0..31
    const int pc = (tid & 7) * 4;      // 0..28

    float acc[4][4];
    #pragma unroll
    for (int i = 0; i < 4; i++)
        #pragma unroll
        for (int j = 0; j < 4; j++) acc[i][j] = 0.0f;

    auto issue_tile = [&](int k0, int buf) {
        // B tile: 64 n-rows x 32 k (already tf32 bits in g_wf)
        #pragma unroll
        for (int p = 0; p < 2; p++) {
            int n = pr + p * 32;
            uint32_t d = (uint32_t)__cvta_generic_to_shared(
                &Bs[buf][n * SSTRIDE + pc]);
            CP_ASYNC16(d, (const float*)g_wf + (size_t)(n0 + n) * INF + k0 + pc);
        }
        if (!is_bf16) {
            // A tile: raw fp32 (tf32 conversion happens at fragment load)
            #pragma unroll
            for (int p = 0; p < 2; p++) {
                int r = pr + p * 32;
                uint32_t d = (uint32_t)__cvta_generic_to_shared(
                    &As[buf][r * SSTRIDE + pc]);
                CP_ASYNC16(d, (const float*)xraw + (size_t)(m0 + r) * INF + k0 + pc);
            }
        } else {
            // bf16 path: LDG 8 vals, convert, STS
            int r = tid >> 2;           // 0..63
            int c = (tid & 3) * 8;      // 0,8,16,24
            uint4 u = *(const uint4*)((const __nv_bfloat16*)xraw +
                                      (size_t)(m0 + r) * INF + k0 + c);
            const __nv_bfloat162* hb = (const __nv_bfloat162*)&u;
            float* dstp = &As[buf][r * SSTRIDE + c];
            #pragma unroll
            for (int j = 0; j < 4; j++) {
                float2 f = __bfloat1622float2(hb[j]);
                dstp[2 * j]     = f.x;
                dstp[2 * j + 1] = f.y;
            }
        }
        CP_COMMIT();
    };

    issue_tile(0, 0);
    int buf = 0;
    for (int i = 0; i < INF / BK; i++) {
        CP_WAIT0();
        __syncthreads();
        if (i < INF / BK - 1) issue_tile((i + 1) * BK, buf ^ 1);

        #pragma unroll
        for (int kk = 0; kk < BK; kk += 8) {
            const float* ap = &As[buf][(mw * 16 + g) * SSTRIDE + kk + t];
            uint32_t a0 = f2tf32(ap[0]);
            uint32_t a1 = f2tf32(ap[8 * SSTRIDE]);
            uint32_t a2 = f2tf32(ap[4]);
            uint32_t a3 = f2tf32(ap[8 * SSTRIDE + 4]);
            #pragma unroll
            for (int nt = 0; nt < 4; nt++) {
                const float* bp = &Bs[buf][(nh2 * 32 + nt * 8 + g) * SSTRIDE + kk + t];
                uint32_t b0 = __float_as_uint(bp[0]);
                uint32_t b1 = __float_as_uint(bp[4]);
                asm volatile(
                    "mma.sync.aligned.m16n8k8.row.col.f32.tf32.tf32.f32 "
                    "{%0,%1,%2,%3}, {%4,%5,%6,%7}, {%8,%9}, {%0,%1,%2,%3};"
                    : "+f"(acc[nt][0]), "+f"(acc[nt][1]),
                      "+f"(acc[nt][2]), "+f"(acc[nt][3])
                    : "r"(a0), "r"(a1), "r"(a2), "r"(a3), "r"(b0), "r"(b1));
            }
        }
        buf ^= 1;
    }

    // Epilogue: store h + fused per-node score dots.
    // D frag: c0=(g,2t) c1=(g,2t+1) c2=(g+8,2t) c3=(g+8,2t+1).
    int mrow = m0 + mw * 16 + g;
    int head = (n0 >> 5) + nh2;        // this warp's head (0..3)
    float ss0 = 0.f, ss1 = 0.f, sd0 = 0.f, sd1 = 0.f;
    #pragma unroll
    for (int nt = 0; nt < 4; nt++) {
        int fl = nt * 8 + 2 * t;       // local f within head, 0..31
        int ncol = n0 + nh2 * 32 + fl;
        *(float2*)&g_h[(size_t)mrow * HDIM + ncol] =
            make_float2(acc[nt][0], acc[nt][1]);
        *(float2*)&g_h[(size_t)(mrow + 8) * HDIM + ncol] =
            make_float2(acc[nt][2], acc[nt][3]);
        float a0s = g_af[fl],        a1s = g_af[fl + 1];
        float a0d = g_af[OUTF + fl], a1d = g_af[OUTF + fl + 1];
        ss0 += acc[nt][0] * a0s + acc[nt][1] * a1s;
        sd0 += acc[nt][0] * a0d + acc[nt][1] * a1d;
        ss1 += acc[nt][2] * a0s + acc[nt][3] * a1s;
        sd1 += acc[nt][2] * a0d + acc[nt][3] * a1d;
    }
    #pragma unroll
    for (int off = 1; off < 4; off <<= 1) {
        ss0 += __shfl_xor_sync(0xffffffffu, ss0, off);
        ss1 += __shfl_xor_sync(0xffffffffu, ss1, off);
        sd0 += __shfl_xor_sync(0xffffffffu, sd0, off);
        sd1 += __shfl_xor_sync(0xffffffffu, sd1, off);
    }
    if (t == 0) {
        g_ssrc[mrow * HEADS + head]       = ss0;
        g_ssrc[(mrow + 8) * HEADS + head] = ss1;
        g_sdst[mrow * HEADS + head]       = sd0;
        g_sdst[(mrow + 8) * HEADS + head] = sd1;
    }
}

// ---------------- kernel 5: convert indices + last-edge (fused) ------------
__global__ void convert_lastedge_kernel(const void* __restrict__ raw) {
    int e = blockIdx.x * blockDim.x + threadIdx.x;
    if (e >= EE) return;
    int s, d;
    if (g_bad_int) {                 // float32 layout
        const float* p = (const float*)raw;
        s = (int)p[e];  d = (int)p[EE + e];
    } else if (g_odd_nonzero) {      // int32 layout
        const int* p = (const int*)raw;
        s = p[e];       d = p[EE + e];
    } else {                         // int64 layout
        const long long* p = (const long long*)raw;
        s = (int)p[e];  d = (int)p[EE + e];
    }
    s = min(max(s, 0), NN - 1);
    d = min(max(d, 0), NN - 1);
    g_src[e] = s;
    g_dst[e] = d;
    atomicMax(&g_last[s], e);
}

// ---------------- kernel 6: aw from last-edge softmax over batch -----------
__global__ void aw_kernel() {
    int gid = blockIdx.x * blockDim.x + threadIdx.x;   // n*HEADS + h
    if (gid >= NN * HEADS) return;
    int hh = gid & (HEADS - 1);
    int n  = gid >> 2;
    int e  = g_last[n];
    float w0 = 0.0f, w1 = 0.0f;
    if (e >= 0) {
        int d = g_dst[e];
        float z0 = g_ssrc[n * HEADS + hh]        + g_sdst[d * HEADS + hh];
        float z1 = g_ssrc[(NN + n) * HEADS + hh] + g_sdst[(NN + d) * HEADS + hh];
        z0 = z0 > 0.0f ? z0 : NEG_SLOPE * z0;
        z1 = z1 > 0.0f ? z1 : NEG_SLOPE * z1;
        float m  = fmaxf(z0, z1);
        float p0 = __expf(z0 - m);
        float p1 = __expf(z1 - m);
        float inv = 1.0f / (p0 + p1);
        w0 = p0 * inv;
        w1 = p1 * inv;
    }
    g_aw[n * HEADS + hh]        = 0.25f * w0;   // fold head-mean
    g_aw[(NN + n) * HEADS + hh] = 0.25f * w1;
}

// ---------------- kernel 7: aggregation, v4 reductions into d_out ----------
__device__ __forceinline__ void red_add_v4(float* ptr, float4 v) {
    asm volatile("red.global.add.v4.f32 [%0], {%1, %2, %3, %4};"
                 :: "l"(ptr), "f"(v.x), "f"(v.y), "f"(v.z), "f"(v.w)
                 : "memory");
}

__global__ __launch_bounds__(256) void agg_kernel(float* __restrict__ out) {
    int gid = blockIdx.x * blockDim.x + threadIdx.x;
    if (gid >= EE * BB * (OUTF / 4)) return;
    int f4 = gid & 7;          // 0..7
    int b  = (gid >> 3) & 1;
    int e  = gid >> 4;

    int src = g_src[e];
    int dst = g_dst[e];

    float4 c = *(const float4*)(g_aw + ((size_t)b * NN + src) * HEADS);

    const float* hp = g_h + ((size_t)b * NN + dst) * HDIM + f4 * 4;
    float4 h0 = __ldg((const float4*)(hp));
    float4 h1 = __ldg((const float4*)(hp + OUTF));
    float4 h2 = __ldg((const float4*)(hp + 2 * OUTF));
    float4 h3 = __ldg((const float4*)(hp + 3 * OUTF));

    float4 v;
    v.x = c.x * h0.x + c.y * h1.x + c.z * h2.x + c.w * h3.x;
    v.y = c.x * h0.y + c.y * h1.y + c.z * h2.y + c.w * h3.y;
    v.z = c.x * h0.z + c.y * h1.z + c.z * h2.z + c.w * h3.z;
    v.w = c.x * h0.w + c.y * h1.w + c.z * h2.w + c.w * h3.w;

    red_add_v4(out + ((size_t)b * NN + src) * OUTF + f4 * 4, v);
}

// ---------------- launch ---------------------------------------------------
extern "C" void kernel_launch(void* const* d_in, const int* in_sizes, int n_in,
                              void* d_out, int out_size) {
    // Rank-based binding: largest -> x, 2nd -> edges, 3rd -> W, smallest -> a
    int order[8];
    int m = n_in < 8 ? n_in : 8;
    for (int i = 0; i < m; i++) order[i] = i;
    for (int i = 0; i < m; i++)
        for (int j = i + 1; j < m; j++)
            if (in_sizes[order[j]] > in_sizes[order[i]]) {
                int t = order[i]; order[i] = order[j]; order[j] = t;
            }
    const void* x  = d_in[m > 0 ? order[0] : 0];
    const void* ei = d_in[m > 1 ? order[1] : 1];
    const void* W  = d_in[m > 2 ? order[2] : 2];
    const void* a  = d_in[m > 3 ? order[3] : 3];

    float* out = (float*)d_out;

    {
        int n = out_size > NN ? out_size : NN;
        init_probe_kernel<<<(n + 255) / 256, 256>>>(out, out_size,
                                                    (const unsigned*)x);  // 1
    }
    fconv_all_kernel<<<(HDIM * INF + 2 * OUTF + 255) / 256, 256>>>(W, a); // 2
    detect_kernel<<<(2 * EE + 255) / 256, 256>>>((const int*)ei);         // 3
    {
        dim3 grid((BB * NN) / BM, 2);
        gemm_tf32<<<grid, 256>>>(x);                                      // 4 <- profiled
    }
    convert_lastedge_kernel<<<(EE + 255) / 256, 256>>>(ei);               // 5
    aw_kernel<<<(NN * HEADS + 255) / 256, 256>>>();                       // 6
    agg_kernel<<<(EE * BB * (OUTF / 4) + 255) / 256, 256>>>(out);         // 7
}